// round 1
// baseline (speedup 1.0000x reference)
#include <cuda_runtime.h>
#include <cstdint>
#include <cstddef>

// Problem constants (fixed shapes for this dataset)
#define NN     4096     // N*N
#define CC     256      // feature dim
#define BB     32       // batch (videos)
#define SS     64       // sentences
#define TPB    128      // threads per block in score kernel (1 proposal each)
#define NTILES 32       // ceil(NN / TPB) worst case
#define NPBLK  (BB*NTILES)

// T_V = T_Q = 0.1  ->  1/t = 10
#define INV_T 10.0f
#define EPSN  1e-12f

// ---------------- device scratch (no allocations allowed) ----------------
__device__ int   g_flat[NN];          // compacted proposal -> flat (i*N+j)
__device__ int   g_P;                 // number of valid proposals
__device__ int   g_scatter[SS];       // sentence -> video index
__device__ float g_sf[SS*CC];         // normalized sentence feats
__device__ float g_partial[NPBLK*SS]; // per-block partial neg-exp sums
__device__ float g_negsum[SS];        // inter-query neg sums
__device__ int   g_pstar[SS];         // per-sentence argmax proposal (flat idx)
__device__ float g_A[SS*SS];          // A[s][t] = dot(topk_video[s], sf[t])

// ---------------- setup: compact mask + scatter indices ----------------
__global__ void setup_kernel(const unsigned char* __restrict__ mask,
                             const int* __restrict__ num_targets) {
    __shared__ int wsum[32];
    __shared__ int mode_s;
    int t = threadIdx.x;                  // 1024 threads, 4 entries each
    if (t == 0) mode_s = (mask[1] != 0);  // byte-bool vs 4-byte encoding
    __syncthreads();
    int mode = mode_s;

    int pred[4], cnt = 0;
#pragma unroll
    for (int k = 0; k < 4; k++) {
        int idx = t * 4 + k;
        int m = mode ? (mask[idx] != 0)
                     : (((const int*)mask)[idx] != 0);
        pred[k] = m; cnt += m;
    }
    int lane = t & 31, w = t >> 5;
    int inc = cnt;
#pragma unroll
    for (int off = 1; off < 32; off <<= 1) {
        int y = __shfl_up_sync(0xffffffffu, inc, off);
        if (lane >= off) inc += y;
    }
    if (lane == 31) wsum[w] = inc;
    __syncthreads();
    if (w == 0) {
        int v = wsum[lane];
#pragma unroll
        for (int off = 1; off < 32; off <<= 1) {
            int y = __shfl_up_sync(0xffffffffu, v, off);
            if (lane >= off) v += y;
        }
        wsum[lane] = v;
    }
    __syncthreads();
    int base = (w ? wsum[w - 1] : 0) + inc - cnt;
#pragma unroll
    for (int k = 0; k < 4; k++) {
        if (pred[k]) g_flat[base++] = t * 4 + k;
    }
    if (t == blockDim.x - 1) g_P = wsum[31];

    if (t == 0) {
        int off = 0;
        for (int b = 0; b < BB && off < SS; b++) {
            int n = num_targets[b];
            for (int k = 0; k < n && off < SS; k++) g_scatter[off++] = b;
        }
    }
}

// ---------------- normalize sentence features ----------------
__global__ void norm_sents(const float* __restrict__ sents) {
    int s = blockIdx.x, c = threadIdx.x;   // SS blocks x CC threads
    __shared__ float sm[CC];
    float x = sents[s * CC + c];
    sm[c] = x * x;
    __syncthreads();
    for (int st = CC / 2; st > 0; st >>= 1) {
        if (c < st) sm[c] += sm[c + st];
        __syncthreads();
    }
    float inv = 1.0f / fmaxf(sqrtf(sm[0]), EPSN);
    g_sf[s * CC + c] = x * inv;
}

// ---------------- per-sentence argmax over gathered iou ----------------
__global__ void argmax_k(const float* __restrict__ iou) {
    int s = blockIdx.x, t = threadIdx.x;   // SS blocks x 256 threads
    int P = g_P;
    __shared__ float bv[256];
    __shared__ int   bi[256];
    float best = -1e30f;
    int bp = 1 << 30;
    for (int p = t; p < P; p += 256) {
        float v = iou[s * NN + g_flat[p]];
        if (v > best) { best = v; bp = p; }   // ascending p => first max kept
    }
    bv[t] = best; bi[t] = bp;
    __syncthreads();
    for (int st = 128; st > 0; st >>= 1) {
        if (t < st) {
            if (bv[t + st] > bv[t] || (bv[t + st] == bv[t] && bi[t + st] < bi[t])) {
                bv[t] = bv[t + st]; bi[t] = bi[t + st];
            }
        }
        __syncthreads();
    }
    if (t == 0) g_pstar[s] = g_flat[bi[0]];
}

// ---------------- main fused score kernel ----------------
// Block = (p-tile, b). Thread owns one proposal p: accumulates the 64
// sentence dots + sum-of-squares in one pass over video_feats, scales by
// rsqrt, exponentiates, masks positives, and block-reduces per-sentence
// negative-exp partial sums (deterministic fixed-order reduction).
#define SCORE_SMEM_FLOATS (SS*CC + SS*4 + SS)
__global__ void score_kernel(const float* __restrict__ video,
                             const float* __restrict__ iou) {
    extern __shared__ float smem[];
    float* sf   = smem;                 // SS*CC
    float* red  = smem + SS * CC;       // SS*4
    int*   scat = (int*)(red + SS * 4); // SS

    const int b    = blockIdx.y;
    const int tile = blockIdx.x;
    const int P    = g_P;
    const int p    = tile * TPB + (int)threadIdx.x;

    for (int i = threadIdx.x; i < SS * CC / 4; i += TPB)
        ((float4*)sf)[i] = ((const float4*)g_sf)[i];
    if (threadIdx.x < SS) scat[threadIdx.x] = g_scatter[threadIdx.x];
    __syncthreads();

    const bool valid = (p < P);
    const int  g = valid ? g_flat[p] : 0;
    const float* vp = video + (size_t)b * CC * NN + g;

    float acc[SS];
#pragma unroll
    for (int s = 0; s < SS; s++) acc[s] = 0.0f;
    float ssq = 0.0f;

    if (valid) {
#pragma unroll 1
        for (int c0 = 0; c0 < CC; c0 += 4) {
            float v0 = vp[(size_t)(c0 + 0) * NN];
            float v1 = vp[(size_t)(c0 + 1) * NN];
            float v2 = vp[(size_t)(c0 + 2) * NN];
            float v3 = vp[(size_t)(c0 + 3) * NN];
            ssq = fmaf(v0, v0, ssq);
            ssq = fmaf(v1, v1, ssq);
            ssq = fmaf(v2, v2, ssq);
            ssq = fmaf(v3, v3, ssq);
#pragma unroll
            for (int s = 0; s < SS; s++) {
                const float4 w = *(const float4*)(sf + s * CC + c0);
                acc[s] = fmaf(w.x, v0, fmaf(w.y, v1, fmaf(w.z, v2, fmaf(w.w, v3, acc[s]))));
            }
        }
    }
    const float inv = valid ? (1.0f / fmaxf(sqrtf(ssq), EPSN)) : 0.0f;

    const int lane = threadIdx.x & 31;
    const int wrp  = threadIdx.x >> 5;
#pragma unroll
    for (int s = 0; s < SS; s++) {
        float e = 0.0f;
        if (valid) {
            bool same = (scat[s] == b);
            float iv = same ? iou[s * NN + g] : 0.0f;
            bool neg = !(same && iv > 0.5f);
            if (neg) e = expf(acc[s] * inv * INV_T);
        }
#pragma unroll
        for (int off = 16; off; off >>= 1)
            e += __shfl_down_sync(0xffffffffu, e, off);
        if (lane == 0) red[s * 4 + wrp] = e;
    }
    __syncthreads();
    if (threadIdx.x < SS) {
        int s = threadIdx.x;
        g_partial[(b * NTILES + tile) * SS + s] =
            red[s * 4 + 0] + red[s * 4 + 1] + red[s * 4 + 2] + red[s * 4 + 3];
    }
}

// ---------------- deterministic reduction of partials ----------------
__global__ void reduce_neg() {
    int s = blockIdx.x;            // SS blocks x 256 threads
    int t = threadIdx.x;
    __shared__ float sm[256];
    float sum = 0.0f;
    for (int i = t; i < NPBLK; i += 256) sum += g_partial[i * SS + s];
    sm[t] = sum;
    __syncthreads();
    for (int st = 128; st > 0; st >>= 1) {
        if (t < st) sm[t] += sm[t + st];
        __syncthreads();
    }
    if (t == 0) g_negsum[s] = sm[0];
}

// ---------------- A[s][t] = dot(normalized topk proposal of s, sf[t]) ----
__global__ void topk_dots(const float* __restrict__ video) {
    int s = blockIdx.x, t = threadIdx.x;   // SS blocks x 256 threads
    __shared__ float tv[CC];
    __shared__ float rs[CC];
    int b = g_scatter[s];
    int g = g_pstar[s];
    float v = video[((size_t)(b * CC + t)) * NN + g];
    rs[t] = v * v;
    __syncthreads();
    for (int st = 128; st > 0; st >>= 1) {
        if (t < st) rs[t] += rs[t + st];
        __syncthreads();
    }
    float inv = 1.0f / fmaxf(sqrtf(rs[0]), EPSN);
    tv[t] = v * inv;
    __syncthreads();
    int lane = t & 31, wrp = t >> 5;
    for (int q = wrp; q < SS; q += 8) {
        float d = 0.0f;
        for (int c = lane; c < CC; c += 32) d += g_sf[q * CC + c] * tv[c];
#pragma unroll
        for (int off = 16; off; off >>= 1)
            d += __shfl_down_sync(0xffffffffu, d, off);
        if (lane == 0) g_A[s * SS + q] = d;
    }
}

// ---------------- final losses ----------------
__global__ void finalize(float* __restrict__ out) {
    __shared__ float l1[SS], l2[SS];
    int s = threadIdx.x;   // SS threads
    float pos = g_A[s * SS + s];
    float nsv = 0.0f;
    for (int u = 0; u < SS; u++)
        if (u != s) nsv += expf(g_A[s * SS + u] * INV_T);
    float pe = expf(pos * INV_T);
    float lv = -(pos * INV_T - logf(pe + nsv));
    float lq = -(pos * INV_T - logf(pe + g_negsum[s]));
    l1[s] = lv; l2[s] = lq;
    __syncthreads();
    for (int st = 32; st > 0; st >>= 1) {
        if (s < st) { l1[s] += l1[s + st]; l2[s] += l2[s + st]; }
        __syncthreads();
    }
    if (s == 0) {
        out[0] = l1[0] / (float)SS;  // loss_inter_video
        out[1] = l2[0] / (float)SS;  // loss_inter_query
    }
}

// ---------------- launcher ----------------
extern "C" void kernel_launch(void* const* d_in, const int* in_sizes, int n_in,
                              void* d_out, int out_size) {
    const float*         video = (const float*)d_in[0];         // [B,C,N,N]
    const float*         sents = (const float*)d_in[1];         // [S,C]
    const int*           ntgt  = (const int*)d_in[2];           // [B]
    const float*         iou   = (const float*)d_in[3];         // [S,N,N]
    const unsigned char* mask  = (const unsigned char*)d_in[4]; // [N,N] bool
    float* out = (float*)d_out;

    const int smem_bytes = SCORE_SMEM_FLOATS * (int)sizeof(float);
    cudaFuncSetAttribute(score_kernel,
                         cudaFuncAttributeMaxDynamicSharedMemorySize, smem_bytes);

    setup_kernel<<<1, 1024>>>(mask, ntgt);
    norm_sents<<<SS, CC>>>(sents);
    argmax_k<<<SS, 256>>>(iou);
    dim3 grid(NTILES, BB);
    score_kernel<<<grid, TPB, smem_bytes>>>(video, iou);
    reduce_neg<<<SS, 256>>>();
    topk_dots<<<SS, 256>>>(video);
    finalize<<<1, SS>>>(out);
}